// round 1
// baseline (speedup 1.0000x reference)
#include <cuda_runtime.h>
#include <math.h>

#define N 2048
#define Q 1024
#define S 512
#define NBINS 20
#define BM 64
#define BN 64
#define BK 16

// ---------------- scratch (device globals; no allocation allowed) ----------
__device__ float d_gcal[(size_t)N * N];   // local-calibrated graph
__device__ float d_rowsum[N];
__device__ float d_colpart[8 * N];        // partial column sums (deterministic 2-stage)
__device__ float d_rs[N];                 // 1/sqrt(rowsum)
__device__ float d_csc[N];                // cw[j]/sqrt(colsum[j])
__device__ float d_t[N];                  // rs*csc  (folded into A)
__device__ float d_probs[NBINS];
__device__ float d_cw[N];
__device__ float d_Ag[(size_t)Q * N];     // gathered+t-scaled query rows
__device__ float d_Bg[(size_t)N * S];     // gathered seed columns
__device__ float d_gq[(size_t)Q * S];     // hop result
__device__ float d_rsq[Q];
__device__ float d_cscs[S];
__device__ float d_part[128 * 3];         // stats partials
__device__ float d_stats[3];              // n_nz, sum, sumsq

__constant__ float c_bases[NBINS] = {
    0.0f, 0.05263157894736842f, 0.10526315789473684f, 0.15789473684210525f,
    0.21052631578947367f, 0.2631578947368421f, 0.3157894736842105f,
    0.3684210526315789f, 0.42105263157894735f, 0.47368421052631576f,
    0.5263157894736842f, 0.5789473684210527f, 0.631578947368421f,
    0.6842105263157895f, 0.7368421052631579f, 0.7894736842105263f,
    0.8421052631578947f, 0.8947368421052632f, 0.9473684210526315f, 1.0f};

// sigma is identical for every bin: (1/19)/50
__device__ __forceinline__ float inv_sigma() {
    const float SIGMA = (float)((1.0 / 19.0) / 50.0);
    return 1.0f / SIGMA; // compile-time folded
}

// ---------------- K0: softmax(calib_w) and cw = softmax(col_weights)*N ------
__global__ void k_prep(const float* __restrict__ calib_w,
                       const float* __restrict__ colw) {
    if (blockIdx.x == 0) {
        if (threadIdx.x == 0) {
            float mx = calib_w[0];
            for (int i = 1; i < NBINS; i++) mx = fmaxf(mx, calib_w[i]);
            float e[NBINS];
            float s = 0.f;
            for (int i = 0; i < NBINS; i++) { e[i] = expf(calib_w[i] - mx); s += e[i]; }
            float inv = 1.0f / s;
            for (int i = 0; i < NBINS; i++) d_probs[i] = e[i] * inv;
        }
    } else {
        __shared__ float red[256];
        int t = threadIdx.x;
        float mx = -1e30f;
        for (int j = t; j < N; j += 256) mx = fmaxf(mx, colw[j]);
        red[t] = mx; __syncthreads();
        for (int o = 128; o > 0; o >>= 1) {
            if (t < o) red[t] = fmaxf(red[t], red[t + o]);
            __syncthreads();
        }
        mx = red[0]; __syncthreads();
        float s = 0.f;
        for (int j = t; j < N; j += 256) s += expf(colw[j] - mx);
        red[t] = s; __syncthreads();
        for (int o = 128; o > 0; o >>= 1) {
            if (t < o) red[t] += red[t + o];
            __syncthreads();
        }
        float inv = (float)N / red[0];
        for (int j = t; j < N; j += 256) d_cw[j] = expf(colw[j] - mx) * inv;
    }
}

// ---------------- K1: local calibration + row sums --------------------------
__global__ void k_calib(const float* __restrict__ graph) {
    int row = blockIdx.x;
    int t = threadIdx.x;
    __shared__ float probs[NBINS];
    __shared__ float red[256];
    if (t < NBINS) probs[t] = d_probs[t];
    __syncthreads();
    const float* grow = graph + (size_t)row * N;
    float* orow = d_gcal + (size_t)row * N;
    const float isig = inv_sigma();
    float rsum = 0.f;
#pragma unroll
    for (int c = 0; c < 8; c++) {
        int j = t + c * 256;
        float g = grow[j];
        float out = 0.f;
        if (g > 0.f) {
            // only bins within |d| <= ~4.5/19 contribute (rest underflow past 1e-23)
            int k0 = (int)floorf(g * 19.f + 0.5f);
            float s = 0.f, sp = 0.f;
#pragma unroll
            for (int kk = 0; kk < 9; kk++) {
                int k = k0 - 4 + kk;
                if (k >= 0 && k < NBINS) {
                    float d = g - c_bases[k];
                    float z = __expf(-d * d * isig);
                    s += z;
                    sp += z * probs[k];
                }
            }
            out = sp / s;
        }
        orow[j] = out;
        rsum += out;
    }
    red[t] = rsum; __syncthreads();
    for (int o = 128; o > 0; o >>= 1) {
        if (t < o) red[t] += red[t + o];
        __syncthreads();
    }
    if (t == 0) d_rowsum[row] = red[0];
}

// ---------------- K2: column sum partials (deterministic) -------------------
__global__ void k_colsum() {
    int col = blockIdx.x * 256 + threadIdx.x;
    int r0 = blockIdx.y * 256;
    float s = 0.f;
#pragma unroll 4
    for (int r = 0; r < 256; r++) s += d_gcal[(size_t)(r0 + r) * N + col];
    d_colpart[blockIdx.y * N + col] = s;
}

// ---------------- K3: per-index scales --------------------------------------
__global__ void k_scales() {
    int j = blockIdx.x * 256 + threadIdx.x;
    float cs = 0.f;
#pragma unroll
    for (int p = 0; p < 8; p++) cs += d_colpart[p * N + j];
    float rsum = d_rowsum[j];
    float rs = (rsum > 0.f) ? rsqrtf(rsum) : 0.f;
    float cc = (cs > 0.f) ? rsqrtf(cs) : 0.f;
    float csc = cc * d_cw[j];
    d_rs[j] = rs;
    d_csc[j] = csc;
    d_t[j] = rs * csc;
    if (blockIdx.x == 0 && threadIdx.x == 0) {
        d_stats[0] = 0.f; d_stats[1] = 0.f; d_stats[2] = 0.f;
    }
}

// ---------------- K4: gather query rows (fold t[k] in) ----------------------
__global__ void k_gatherA(const int* __restrict__ qid) {
    int q = blockIdx.x;
    int t = threadIdx.x;
    int qq = qid[q];
    const float* src = d_gcal + (size_t)qq * N;
    float* dst = d_Ag + (size_t)q * N;
#pragma unroll
    for (int c = 0; c < 8; c++) {
        int j = t + c * 256;
        dst[j] = src[j] * d_t[j];
    }
    if (t == 0) d_rsq[q] = d_rs[qq];
}

// ---------------- K5: gather seed columns -----------------------------------
__global__ void k_gatherB(const int* __restrict__ sid) {
    int k = blockIdx.x;
    int t = threadIdx.x;
    const float* src = d_gcal + (size_t)k * N;
    float* dst = d_Bg + (size_t)k * S;
#pragma unroll
    for (int c = 0; c < 4; c++) {
        int s = t + c * 128;
        dst[s] = src[sid[s]];
    }
    if (k == 0) {
#pragma unroll
        for (int c = 0; c < 4; c++) {
            int s = t + c * 128;
            d_cscs[s] = d_csc[sid[s]];
        }
    }
}

// ---------------- K6: hop GEMM 1024x512x2048 fp32, scaled+masked epilogue ---
__global__ __launch_bounds__(256) void k_gemm(const int* __restrict__ qid,
                                              const int* __restrict__ sid) {
    __shared__ float As[BK][BM + 4]; // +4 pad keeps float4 alignment, cuts STS conflicts
    __shared__ float Bs[BK][BN];
    int tid = threadIdx.x;
    int tx = tid & 15, ty = tid >> 4;
    int bx = blockIdx.x * BN, by = blockIdx.y * BM;

    float acc[4][4] = {};

    int am = tid >> 2;            // 0..63
    int ak = (tid & 3) << 2;      // 0,4,8,12
    const float* aptr = d_Ag + (size_t)(by + am) * N + ak;
    int bk = tid >> 4;            // 0..15
    int bn = (tid & 15) << 2;
    const float* bptr = d_Bg + (size_t)bk * S + bx + bn;

    for (int kb = 0; kb < N; kb += BK) {
        float4 av = *(const float4*)(aptr + kb);
        float4 bv = *(const float4*)(bptr + (size_t)kb * S);
        As[ak + 0][am] = av.x;
        As[ak + 1][am] = av.y;
        As[ak + 2][am] = av.z;
        As[ak + 3][am] = av.w;
        *(float4*)&Bs[bk][bn] = bv;
        __syncthreads();
#pragma unroll
        for (int k = 0; k < BK; k++) {
            float4 a = *(const float4*)&As[k][ty << 2];
            float4 b = *(const float4*)&Bs[k][tx << 2];
            acc[0][0] += a.x * b.x; acc[0][1] += a.x * b.y;
            acc[0][2] += a.x * b.z; acc[0][3] += a.x * b.w;
            acc[1][0] += a.y * b.x; acc[1][1] += a.y * b.y;
            acc[1][2] += a.y * b.z; acc[1][3] += a.y * b.w;
            acc[2][0] += a.z * b.x; acc[2][1] += a.z * b.y;
            acc[2][2] += a.z * b.z; acc[2][3] += a.z * b.w;
            acc[3][0] += a.w * b.x; acc[3][1] += a.w * b.y;
            acc[3][2] += a.w * b.z; acc[3][3] += a.w * b.w;
        }
        __syncthreads();
    }

#pragma unroll
    for (int i = 0; i < 4; i++) {
        int q = by + (ty << 2) + i;
        float rq = d_rsq[q];
        int qq = qid[q];
#pragma unroll
        for (int j = 0; j < 4; j++) {
            int s = bx + (tx << 2) + j;
            float v = acc[i][j] * rq * d_cscs[s];
            if (sid[s] == qq) v = 0.f;   // diag mask
            d_gq[(size_t)q * S + s] = v;
        }
    }
}

// ---------------- K7: global stats (deterministic two-stage) ----------------
__global__ void k_stats() {
    __shared__ float r0[256], r1[256], r2[256];
    int t = threadIdx.x;
    size_t base = (size_t)blockIdx.x * 4096;
    float c = 0.f, s = 0.f, q = 0.f;
#pragma unroll
    for (int i = 0; i < 16; i++) {
        float g = d_gq[base + t + i * 256];
        if (g > 0.f) c += 1.f;
        s += g;
        q += g * g;
    }
    r0[t] = c; r1[t] = s; r2[t] = q;
    __syncthreads();
    for (int o = 128; o > 0; o >>= 1) {
        if (t < o) { r0[t] += r0[t + o]; r1[t] += r1[t + o]; r2[t] += r2[t + o]; }
        __syncthreads();
    }
    if (t == 0) {
        d_part[blockIdx.x * 3 + 0] = r0[0];
        d_part[blockIdx.x * 3 + 1] = r1[0];
        d_part[blockIdx.x * 3 + 2] = r2[0];
    }
}

__global__ void k_stats2() {
    __shared__ float r0[128], r1[128], r2[128];
    int t = threadIdx.x;
    r0[t] = d_part[t * 3 + 0];
    r1[t] = d_part[t * 3 + 1];
    r2[t] = d_part[t * 3 + 2];
    __syncthreads();
    for (int o = 64; o > 0; o >>= 1) {
        if (t < o) { r0[t] += r0[t + o]; r1[t] += r1[t + o]; r2[t] += r2[t + o]; }
        __syncthreads();
    }
    if (t == 0) {
        d_stats[0] = r0[0]; d_stats[1] = r1[0]; d_stats[2] = r2[0];
    }
}

// ---------------- K8: standardize, powers, ELU, row-normalize ---------------
__global__ void k_final(const float* __restrict__ gw,
                        const float* __restrict__ gb,
                        float* __restrict__ out) {
    int q = blockIdx.x, t = threadIdx.x;
    __shared__ float red[256];
    float s0 = d_stats[0], s1 = d_stats[1], s2 = d_stats[2];
    float mean = s1 / s0;
    float var = fmaxf(s2 / s0 - mean * mean, 1e-30f);
    float istd = rsqrtf(var);
    float w0 = gw[0], w1 = gw[1], w2 = gw[2], w3 = gw[3], w4 = gw[4];
    float b = gb[0];

    float y[2];
#pragma unroll
    for (int c = 0; c < 2; c++) {
        float g = d_gq[(size_t)q * S + t + c * 256];
        float yy = 0.f;
        if (g > 0.f) {
            float x = (g - mean) * istd;
            float m = fabsf(x);
            float sq = (m > 0.f) ? copysignf(sqrtf(m), x) : 0.f;
            float xm = x * m;
            float p = b + w0 * x + w1 * sq + w2 * xm + w3 * xm * m + w4 * xm * m * m;
            yy = ((p > 0.f) ? p : expm1f(p)) + 1.f;
        }
        y[c] = yy;
    }
    red[t] = y[0] + y[1];
    __syncthreads();
    for (int o = 128; o > 0; o >>= 1) {
        if (t < o) red[t] += red[t + o];
        __syncthreads();
    }
    float tot = red[0];
    float inv = (tot != 0.f) ? 1.0f / tot : 0.f;
    out[(size_t)q * S + t] = y[0] * inv;
    out[(size_t)q * S + t + 256] = y[1] * inv;
}

// ---------------- launch ----------------------------------------------------
extern "C" void kernel_launch(void* const* d_in, const int* in_sizes, int n_in,
                              void* d_out, int out_size) {
    const float* graph    = (const float*)d_in[0];
    const float* calib_w  = (const float*)d_in[1];
    const float* global_w = (const float*)d_in[2];
    const float* global_b = (const float*)d_in[3];
    const float* col_w    = (const float*)d_in[4];
    const int*   qid      = (const int*)d_in[5];
    const int*   sid      = (const int*)d_in[6];
    float* out = (float*)d_out;

    k_prep<<<2, 256>>>(calib_w, col_w);
    k_calib<<<N, 256>>>(graph);
    k_colsum<<<dim3(8, 8), 256>>>();
    k_scales<<<8, 256>>>();
    k_gatherA<<<Q, 256>>>(qid);
    k_gatherB<<<N, 128>>>(sid);
    k_gemm<<<dim3(S / BN, Q / BM), 256>>>(qid, sid);
    k_stats<<<128, 256>>>();
    k_stats2<<<1, 128>>>();
    k_final<<<Q, 256>>>(global_w, global_b, out);
}

// round 6
// speedup vs baseline: 2.5625x; 2.5625x over previous
#include <cuda_runtime.h>
#include <cuda_bf16.h>
#include <cstdint>
#include <math.h>

#define N 2048
#define Q 1024
#define S 512
#define NBINS 20
#define FTAB 8192

// ---------------- scratch (device globals; no allocation allowed) ----------
__device__ float d_gcal[(size_t)N * N];
__device__ float d_rowsum[N];
__device__ float d_colpart[8 * N];
__device__ float d_rs[N];
__device__ float d_csc[N];
__device__ float d_t[N];
__device__ float d_cw[N];
__device__ float d_ftab[FTAB + 1];
__device__ __nv_bfloat16 d_Ahi[(size_t)Q * N];
__device__ __nv_bfloat16 d_Amid[(size_t)Q * N];
__device__ __nv_bfloat16 d_Bhi[(size_t)S * N];
__device__ __nv_bfloat16 d_Bmid[(size_t)S * N];
__device__ float d_gq[(size_t)Q * S];
__device__ float d_rsq[Q];
__device__ float d_cscs[S];
__device__ float d_part[128 * 3];
__device__ float d_stats[3];

// ---------------- helpers ---------------------------------------------------
__device__ __forceinline__ uint32_t smem_u32(const void* p) {
    uint32_t a;
    asm("{ .reg .u64 t; cvta.to.shared.u64 t, %1; cvt.u32.u64 %0, t; }"
        : "=r"(a) : "l"(p));
    return a;
}
__device__ __forceinline__ void ldsm4(uint32_t (&r)[4], uint32_t addr) {
    asm volatile(
        "ldmatrix.sync.aligned.m8n8.x4.shared.b16 {%0,%1,%2,%3}, [%4];"
        : "=r"(r[0]), "=r"(r[1]), "=r"(r[2]), "=r"(r[3]) : "r"(addr));
}
__device__ __forceinline__ void mma16816(float (&d)[4], const uint32_t (&a)[4],
                                         uint32_t b0, uint32_t b1) {
    asm volatile(
        "mma.sync.aligned.m16n8k16.row.col.f32.bf16.bf16.f32 "
        "{%0,%1,%2,%3}, {%4,%5,%6,%7}, {%8,%9}, {%0,%1,%2,%3};"
        : "+f"(d[0]), "+f"(d[1]), "+f"(d[2]), "+f"(d[3])
        : "r"(a[0]), "r"(a[1]), "r"(a[2]), "r"(a[3]), "r"(b0), "r"(b1));
}

// ---------------- K0: probs+table (blocks 0-15), cw softmax (block 16) ------
__global__ void k_prep(const float* __restrict__ calib_w,
                       const float* __restrict__ colw) {
    int t = threadIdx.x;
    if (blockIdx.x < 16) {
        float w[NBINS];
#pragma unroll
        for (int i = 0; i < NBINS; i++) w[i] = calib_w[i];
        float mx = w[0];
#pragma unroll
        for (int i = 1; i < NBINS; i++) mx = fmaxf(mx, w[i]);
        float e[NBINS], s = 0.f;
#pragma unroll
        for (int i = 0; i < NBINS; i++) { e[i] = expf(w[i] - mx); s += e[i]; }
        float inv = 1.0f / s;
        // 16 blocks x 256 threads, stride 4096 covers all FTAB+1 entries
        for (int i = blockIdx.x * 256 + t; i <= FTAB; i += 16 * 256) {
            float g = (float)i * (1.0f / FTAB);
            float zs = 0.f, zp = 0.f;
#pragma unroll
            for (int k = 0; k < NBINS; k++) {
                float d = g - (float)k * (1.0f / 19.0f);
                float z = expf(-d * d * 950.0f);
                zs += z;
                zp += z * (e[k] * inv);
            }
            d_ftab[i] = zp / zs;
        }
    } else {
        __shared__ float red[256];
        float mx = -1e30f;
        for (int j = t; j < N; j += 256) mx = fmaxf(mx, colw[j]);
        red[t] = mx; __syncthreads();
        for (int o = 128; o > 0; o >>= 1) {
            if (t < o) red[t] = fmaxf(red[t], red[t + o]);
            __syncthreads();
        }
        mx = red[0]; __syncthreads();
        float s = 0.f;
        for (int j = t; j < N; j += 256) s += expf(colw[j] - mx);
        red[t] = s; __syncthreads();
        for (int o = 128; o > 0; o >>= 1) {
            if (t < o) red[t] += red[t + o];
            __syncthreads();
        }
        float inv = (float)N / red[0];
        for (int j = t; j < N; j += 256) d_cw[j] = expf(colw[j] - mx) * inv;
    }
}

// ---------------- K1: table-based local calibration + row sums --------------
__global__ __launch_bounds__(256) void k_calib(const float* __restrict__ graph) {
    __shared__ float tab[FTAB + 1];
    __shared__ float red[256];
    int t = threadIdx.x;
    for (int i = t; i <= FTAB; i += 256) tab[i] = d_ftab[i];
    __syncthreads();
    int row0 = blockIdx.x * 8;
    for (int r = 0; r < 8; r++) {
        const float* grow = graph + (size_t)(row0 + r) * N;
        float* orow = d_gcal + (size_t)(row0 + r) * N;
        float rsum = 0.f;
#pragma unroll
        for (int c = 0; c < 8; c++) {
            int j = t + c * 256;
            float g = grow[j];
            float out = 0.f;
            if (g > 0.f) {
                float u = g * (float)FTAB;
                int i = min((int)u, FTAB - 1);
                float fr = u - (float)i;
                float f0 = tab[i], f1 = tab[i + 1];
                out = f0 + fr * (f1 - f0);
            }
            orow[j] = out;
            rsum += out;
        }
        red[t] = rsum; __syncthreads();
        for (int o = 128; o > 0; o >>= 1) {
            if (t < o) red[t] += red[t + o];
            __syncthreads();
        }
        if (t == 0) d_rowsum[row0 + r] = red[0];
        __syncthreads();
    }
}

// ---------------- K2: column sum partials -----------------------------------
__global__ void k_colsum() {
    int col = blockIdx.x * 256 + threadIdx.x;
    int r0 = blockIdx.y * 256;
    float s = 0.f;
#pragma unroll 4
    for (int r = 0; r < 256; r++) s += d_gcal[(size_t)(r0 + r) * N + col];
    d_colpart[blockIdx.y * N + col] = s;
}

// ---------------- K3: per-index scales --------------------------------------
__global__ void k_scales() {
    int j = blockIdx.x * 256 + threadIdx.x;
    float cs = 0.f;
#pragma unroll
    for (int p = 0; p < 8; p++) cs += d_colpart[p * N + j];
    float rsum = d_rowsum[j];
    float rs = (rsum > 0.f) ? rsqrtf(rsum) : 0.f;
    float cc = (cs > 0.f) ? rsqrtf(cs) : 0.f;
    float csc = cc * d_cw[j];
    d_rs[j] = rs;
    d_csc[j] = csc;
    d_t[j] = rs * csc;
}

// ---------------- K4: gather query rows, fold t[k], bf16 hi/mid split -------
__global__ void k_gatherA(const int* __restrict__ qid) {
    int q = blockIdx.x;
    int t = threadIdx.x;
    int qq = qid[q];
    const float* src = d_gcal + (size_t)qq * N;
#pragma unroll
    for (int c = 0; c < 8; c++) {
        int j = t + c * 256;
        float a = src[j] * d_t[j];
        __nv_bfloat16 hi = __float2bfloat16(a);
        __nv_bfloat16 mid = __float2bfloat16(a - __bfloat162float(hi));
        d_Ahi[(size_t)q * N + j] = hi;
        d_Amid[(size_t)q * N + j] = mid;
    }
    if (t == 0) d_rsq[q] = d_rs[qq];
}

// ---------------- K5: gather seed columns transposed [S][K], split ----------
__global__ void k_gatherB(const int* __restrict__ sid) {
    int s = blockIdx.x;
    int t = threadIdx.x;
    int col = sid[s];
#pragma unroll
    for (int c = 0; c < 8; c++) {
        int k = t + c * 256;
        float b = d_gcal[(size_t)k * N + col];
        __nv_bfloat16 hi = __float2bfloat16(b);
        __nv_bfloat16 mid = __float2bfloat16(b - __bfloat162float(hi));
        d_Bhi[(size_t)s * N + k] = hi;
        d_Bmid[(size_t)s * N + k] = mid;
    }
    if (t == 0) d_cscs[s] = d_csc[col];
}

// ---------------- K6: HMMA GEMM  C[1024x512] = A[1024x2048] * B[512x2048]^T -
// 64x64 CTA tile, BK=32, double-buffered SMEM with XOR swizzle, 8 warps of
// 32x16 tiles, 3 bf16 MMAs per k16 (hi*hi + hi*mid + mid*hi) -> fp32 grade.
#define TILE_BYTES 16384   // per stage: Ahi 4K | Amid 4K | Bhi 4K | Bmid 4K
__global__ __launch_bounds__(256) void k_gemm_mma(const int* __restrict__ qid,
                                                  const int* __restrict__ sid) {
    __shared__ __align__(128) char sm[2 * TILE_BYTES];
    int tid = threadIdx.x, lane = tid & 31, wid = tid >> 5;
    int bx = blockIdx.x, by = blockIdx.y;
    uint32_t sb = smem_u32(sm);

    // gmem->smem mapping: thread -> (row lr, 16-byte chunk lc) of a 64x64B tile
    int lr = tid >> 2;
    int lc = (tid & 3) * 16;
    uint32_t lsw = (uint32_t)(lr * 64 + lc) ^ ((uint32_t)(lr & 7) << 4);
    const char* pAh = (const char*)d_Ahi  + (size_t)(by * 64 + lr) * 4096 + lc;
    const char* pAm = (const char*)d_Amid + (size_t)(by * 64 + lr) * 4096 + lc;
    const char* pBh = (const char*)d_Bhi  + (size_t)(bx * 64 + lr) * 4096 + lc;
    const char* pBm = (const char*)d_Bmid + (size_t)(bx * 64 + lr) * 4096 + lc;

    float acc[2][2][4];
#pragma unroll
    for (int i = 0; i < 2; i++)
#pragma unroll
        for (int j = 0; j < 2; j++)
#pragma unroll
            for (int k = 0; k < 4; k++) acc[i][j][k] = 0.f;

    int wm = wid & 1, wn = wid >> 1;

    uint4 ra, rb, rc, rd;
    // prologue: stage 0
    ra = *(const uint4*)(pAh); rb = *(const uint4*)(pAm);
    rc = *(const uint4*)(pBh); rd = *(const uint4*)(pBm);
    *(uint4*)(sm + lsw)         = ra;
    *(uint4*)(sm + 4096 + lsw)  = rb;
    *(uint4*)(sm + 8192 + lsw)  = rc;
    *(uint4*)(sm + 12288 + lsw) = rd;

    for (int kb = 0; kb < 64; kb++) {
        int b = kb & 1;
        if (kb < 63) {
            int o = (kb + 1) * 64;
            ra = *(const uint4*)(pAh + o); rb = *(const uint4*)(pAm + o);
            rc = *(const uint4*)(pBh + o); rd = *(const uint4*)(pBm + o);
        }
        __syncthreads();
        uint32_t base = sb + b * TILE_BYTES;

        // B fragments for this k32 (both k16 halves at once via x4)
        uint32_t bh[2][4], bm[2][4];
#pragma unroll
        for (int ni = 0; ni < 2; ni++) {
            int row = wn * 16 + ni * 8 + (lane & 7);
            uint32_t off = (uint32_t)(row * 64 + ((lane >> 3) * 16));
            uint32_t sw = off ^ ((uint32_t)(row & 7) << 4);
            ldsm4(bh[ni], base + 8192 + sw);
            ldsm4(bm[ni], base + 12288 + sw);
        }
#pragma unroll
        for (int k16 = 0; k16 < 2; k16++) {
            uint32_t ah[2][4], am[2][4];
#pragma unroll
            for (int mi = 0; mi < 2; mi++) {
                int row = wm * 32 + mi * 16 + (lane & 15);
                uint32_t off = (uint32_t)(row * 64 + k16 * 32 + ((lane >> 4) * 16));
                uint32_t sw = off ^ ((uint32_t)(row & 7) << 4);
                ldsm4(ah[mi], base + sw);
                ldsm4(am[mi], base + 4096 + sw);
            }
#pragma unroll
            for (int mi = 0; mi < 2; mi++)
#pragma unroll
                for (int ni = 0; ni < 2; ni++) {
                    mma16816(acc[mi][ni], ah[mi], bh[ni][k16 * 2], bh[ni][k16 * 2 + 1]);
                    mma16816(acc[mi][ni], ah[mi], bm[ni][k16 * 2], bm[ni][k16 * 2 + 1]);
                    mma16816(acc[mi][ni], am[mi], bh[ni][k16 * 2], bh[ni][k16 * 2 + 1]);
                }
        }
        if (kb < 63) {
            char* so = sm + (1 - b) * TILE_BYTES;
            *(uint4*)(so + lsw)         = ra;
            *(uint4*)(so + 4096 + lsw)  = rb;
            *(uint4*)(so + 8192 + lsw)  = rc;
            *(uint4*)(so + 12288 + lsw) = rd;
        }
    }

    // epilogue: scale by rs[q]*csc[s], zero diagonal, write gq
#pragma unroll
    for (int mi = 0; mi < 2; mi++) {
        int r0 = by * 64 + wm * 32 + mi * 16 + (lane >> 2);
#pragma unroll
        for (int half = 0; half < 2; half++) {
            int r = r0 + half * 8;
            float rq = d_rsq[r];
            int qq = qid[r];
#pragma unroll
            for (int ni = 0; ni < 2; ni++) {
                int c0 = bx * 64 + wn * 16 + ni * 8 + (lane & 3) * 2;
                float v0 = acc[mi][ni][half * 2 + 0] * rq * d_cscs[c0];
                float v1 = acc[mi][ni][half * 2 + 1] * rq * d_cscs[c0 + 1];
                if (sid[c0] == qq) v0 = 0.f;
                if (sid[c0 + 1] == qq) v1 = 0.f;
                *(float2*)&d_gq[(size_t)r * S + c0] = make_float2(v0, v1);
            }
        }
    }
}

// ---------------- K7: global stats (deterministic two-stage) ----------------
__global__ void k_stats() {
    __shared__ float r0[256], r1[256], r2[256];
    int t = threadIdx.x;
    size_t base = (size_t)blockIdx.x * 4096;
    float c = 0.f, s = 0.f, q = 0.f;
#pragma unroll
    for (int i = 0; i < 16; i++) {
        float g = d_gq[base + t + i * 256];
        if (g > 0.f) c += 1.f;
        s += g;
        q += g * g;
    }
    r0[t] = c; r1[t] = s; r2[t] = q;
    __syncthreads();
    for (int o = 128; o > 0; o >>= 1) {
        if (t < o) { r0[t] += r0[t + o]; r1[t] += r1[t + o]; r2[t] += r2[t + o]; }
        __syncthreads();
    }
    if (t == 0) {
        d_part[blockIdx.x * 3 + 0] = r0[0];
        d_part[blockIdx.x * 3 + 1] = r1[0];
        d_part[blockIdx.x * 3 + 2] = r2[0];
    }
}

__global__ void k_stats2() {
    __shared__ float r0[128], r1[128], r2[128];
    int t = threadIdx.x;
    r0[t] = d_part[t * 3 + 0];
    r1[t] = d_part[t * 3 + 1];
    r2[t] = d_part[t * 3 + 2];
    __syncthreads();
    for (int o = 64; o > 0; o >>= 1) {
        if (t < o) { r0[t] += r0[t + o]; r1[t] += r1[t + o]; r2[t] += r2[t + o]; }
        __syncthreads();
    }
    if (t == 0) {
        d_stats[0] = r0[0]; d_stats[1] = r1[0]; d_stats[2] = r2[0];
    }
}

// ---------------- K8: standardize, powers, ELU, row-normalize ---------------
__global__ void k_final(const float* __restrict__ gw,
                        const float* __restrict__ gb,
                        float* __restrict__ out) {
    int q = blockIdx.x, t = threadIdx.x;
    __shared__ float red[256];
    float s0 = d_stats[0], s1 = d_stats[1], s2 = d_stats[2];
    float mean = s1 / s0;
    float var = fmaxf(s2 / s0 - mean * mean, 1e-30f);
    float istd = rsqrtf(var);
    float w0 = gw[0], w1 = gw[1], w2 = gw[2], w3 = gw[3], w4 = gw[4];
    float b = gb[0];

    float y[2];
#pragma unroll
    for (int c = 0; c < 2; c++) {
        float g = d_gq[(size_t)q * S + t + c * 256];
        float yy = 0.f;
        if (g > 0.f) {
            float x = (g - mean) * istd;
            float m = fabsf(x);
            float sq = (m > 0.f) ? copysignf(sqrtf(m), x) : 0.f;
            float xm = x * m;
            float p = b + w0 * x + w1 * sq + w2 * xm + w3 * xm * m + w4 * xm * m * m;
            yy = ((p > 0.f) ? p : expm1f(p)) + 1.f;
        }
        y[c] = yy;
    }
    red[t] = y[0] + y[1];
    __syncthreads();
    for (int o = 128; o > 0; o >>= 1) {
        if (t < o) red[t] += red[t + o];
        __syncthreads();
    }
    float tot = red[0];
    float inv = (tot != 0.f) ? 1.0f / tot : 0.f;
    out[(size_t)q * S + t] = y[0] * inv;
    out[(size_t)q * S + t + 256] = y[1] * inv;
}

// ---------------- launch ----------------------------------------------------
extern "C" void kernel_launch(void* const* d_in, const int* in_sizes, int n_in,
                              void* d_out, int out_size) {
    const float* graph    = (const float*)d_in[0];
    const float* calib_w  = (const float*)d_in[1];
    const float* global_w = (const float*)d_in[2];
    const float* global_b = (const float*)d_in[3];
    const float* col_w    = (const float*)d_in[4];
    const int*   qid      = (const int*)d_in[5];
    const int*   sid      = (const int*)d_in[6];
    float* out = (float*)d_out;

    k_prep<<<17, 256>>>(calib_w, col_w);
    k_calib<<<256, 256>>>(graph);
    k_colsum<<<dim3(8, 8), 256>>>();
    k_scales<<<8, 256>>>();
    k_gatherA<<<Q, 256>>>(qid);
    k_gatherB<<<S, 256>>>(sid);
    k_gemm_mma<<<dim3(8, 16), 256>>>(qid, sid);
    k_stats<<<128, 256>>>();
    k_stats2<<<1, 128>>>();
    k_final<<<Q, 256>>>(global_w, global_b, out);
}

// round 7
// speedup vs baseline: 2.9577x; 1.1542x over previous
#include <cuda_runtime.h>
#include <cuda_bf16.h>
#include <cstdint>
#include <math.h>

#define N 2048
#define Q 1024
#define S 512
#define NBINS 20
#define FTAB 8192

// ---------------- scratch (device globals; no allocation allowed) ----------
__device__ float d_gcal[(size_t)N * N];
__device__ float d_rowsum[N];
__device__ float d_cp[256 * N];           // per-calib-block column partials
__device__ float d_rs[N];
__device__ float d_csc[N];
__device__ float d_t[N];
__device__ float d_cw[N];
__device__ float d_ftab[FTAB + 1];
__device__ __nv_bfloat16 d_Ahi[(size_t)Q * N];
__device__ __nv_bfloat16 d_Amid[(size_t)Q * N];
__device__ __nv_bfloat16 d_Bhi[(size_t)S * N];
__device__ __nv_bfloat16 d_Bmid[(size_t)S * N];
__device__ float d_gq[(size_t)Q * S];
__device__ float d_rsq[Q];
__device__ float d_cscs[S];
__device__ float d_part[128 * 3];         // per-GEMM-CTA stats partials
__device__ float d_stats[3];
__device__ unsigned int d_ctr = 0;        // last-CTA counter (self-resetting)

// ---------------- helpers ---------------------------------------------------
__device__ __forceinline__ uint32_t smem_u32(const void* p) {
    uint32_t a;
    asm("{ .reg .u64 t; cvta.to.shared.u64 t, %1; cvt.u32.u64 %0, t; }"
        : "=r"(a) : "l"(p));
    return a;
}
__device__ __forceinline__ void ldsm4(uint32_t (&r)[4], uint32_t addr) {
    asm volatile(
        "ldmatrix.sync.aligned.m8n8.x4.shared.b16 {%0,%1,%2,%3}, [%4];"
        : "=r"(r[0]), "=r"(r[1]), "=r"(r[2]), "=r"(r[3]) : "r"(addr));
}
__device__ __forceinline__ void mma16816(float (&d)[4], const uint32_t (&a)[4],
                                         uint32_t b0, uint32_t b1) {
    asm volatile(
        "mma.sync.aligned.m16n8k16.row.col.f32.bf16.bf16.f32 "
        "{%0,%1,%2,%3}, {%4,%5,%6,%7}, {%8,%9}, {%0,%1,%2,%3};"
        : "+f"(d[0]), "+f"(d[1]), "+f"(d[2]), "+f"(d[3])
        : "r"(a[0]), "r"(a[1]), "r"(a[2]), "r"(a[3]), "r"(b0), "r"(b1));
}

// ---------------- K0: probs+table (blocks 0-15), cw softmax (block 16) ------
__global__ void k_prep(const float* __restrict__ calib_w,
                       const float* __restrict__ colw) {
    int t = threadIdx.x;
    if (blockIdx.x < 16) {
        float w[NBINS];
#pragma unroll
        for (int i = 0; i < NBINS; i++) w[i] = calib_w[i];
        float mx = w[0];
#pragma unroll
        for (int i = 1; i < NBINS; i++) mx = fmaxf(mx, w[i]);
        float e[NBINS], s = 0.f;
#pragma unroll
        for (int i = 0; i < NBINS; i++) { e[i] = expf(w[i] - mx); s += e[i]; }
        float inv = 1.0f / s;
        for (int i = blockIdx.x * 256 + t; i <= FTAB; i += 16 * 256) {
            float g = (float)i * (1.0f / FTAB);
            float zs = 0.f, zp = 0.f;
#pragma unroll
            for (int k = 0; k < NBINS; k++) {
                float d = g - (float)k * (1.0f / 19.0f);
                float z = expf(-d * d * 950.0f);
                zs += z;
                zp += z * (e[k] * inv);
            }
            d_ftab[i] = zp / zs;
        }
    } else {
        __shared__ float red[256];
        float mx = -1e30f;
        for (int j = t; j < N; j += 256) mx = fmaxf(mx, colw[j]);
        red[t] = mx; __syncthreads();
        for (int o = 128; o > 0; o >>= 1) {
            if (t < o) red[t] = fmaxf(red[t], red[t + o]);
            __syncthreads();
        }
        mx = red[0]; __syncthreads();
        float s = 0.f;
        for (int j = t; j < N; j += 256) s += expf(colw[j] - mx);
        red[t] = s; __syncthreads();
        for (int o = 128; o > 0; o >>= 1) {
            if (t < o) red[t] += red[t + o];
            __syncthreads();
        }
        float inv = (float)N / red[0];
        for (int j = t; j < N; j += 256) d_cw[j] = expf(colw[j] - mx) * inv;
    }
}

// ---------------- K1: calibration + row sums + column partials --------------
__global__ __launch_bounds__(256) void k_calib(const float* __restrict__ graph) {
    __shared__ float tab[FTAB + 1];
    __shared__ float red[256];
    int t = threadIdx.x;
    for (int i = t; i <= FTAB; i += 256) tab[i] = d_ftab[i];
    __syncthreads();
    int row0 = blockIdx.x * 8;
    float colacc[8] = {0.f, 0.f, 0.f, 0.f, 0.f, 0.f, 0.f, 0.f};
    for (int r = 0; r < 8; r++) {
        const float* grow = graph + (size_t)(row0 + r) * N;
        float* orow = d_gcal + (size_t)(row0 + r) * N;
        float rsum = 0.f;
#pragma unroll
        for (int c = 0; c < 8; c++) {
            int j = t + c * 256;
            float g = grow[j];
            float out = 0.f;
            if (g > 0.f) {
                float u = g * (float)FTAB;
                int i = min((int)u, FTAB - 1);
                float fr = u - (float)i;
                float f0 = tab[i], f1 = tab[i + 1];
                out = f0 + fr * (f1 - f0);
            }
            orow[j] = out;
            rsum += out;
            colacc[c] += out;
        }
        red[t] = rsum; __syncthreads();
        for (int o = 128; o > 0; o >>= 1) {
            if (t < o) red[t] += red[t + o];
            __syncthreads();
        }
        if (t == 0) d_rowsum[row0 + r] = red[0];
        __syncthreads();
    }
#pragma unroll
    for (int c = 0; c < 8; c++)
        d_cp[blockIdx.x * N + t + c * 256] = colacc[c];
}

// ---------------- K2: column sums (256 partials) + all per-index scales -----
__global__ void k_colsum_scales() {
    int j = blockIdx.x * 256 + threadIdx.x;
    float cs = 0.f;
#pragma unroll 8
    for (int p = 0; p < 256; p++) cs += d_cp[p * N + j];
    float rsum = d_rowsum[j];
    float rs = (rsum > 0.f) ? rsqrtf(rsum) : 0.f;
    float cc = (cs > 0.f) ? rsqrtf(cs) : 0.f;
    float csc = cc * d_cw[j];
    d_rs[j] = rs;
    d_csc[j] = csc;
    d_t[j] = rs * csc;
}

// ---------------- K3: merged gathers (blocks [0,Q): A rows, [Q,Q+S): B cols)
__global__ void k_gather(const int* __restrict__ qid, const int* __restrict__ sid) {
    int t = threadIdx.x;
    if (blockIdx.x < Q) {
        int q = blockIdx.x;
        int qq = qid[q];
        const float* src = d_gcal + (size_t)qq * N;
#pragma unroll
        for (int c = 0; c < 8; c++) {
            int j = t + c * 256;
            float a = src[j] * d_t[j];
            __nv_bfloat16 hi = __float2bfloat16(a);
            __nv_bfloat16 mid = __float2bfloat16(a - __bfloat162float(hi));
            d_Ahi[(size_t)q * N + j] = hi;
            d_Amid[(size_t)q * N + j] = mid;
        }
        if (t == 0) d_rsq[q] = d_rs[qq];
    } else {
        int s = blockIdx.x - Q;
        int col = sid[s];
#pragma unroll
        for (int c = 0; c < 8; c++) {
            int k = t + c * 256;
            float b = d_gcal[(size_t)k * N + col];
            __nv_bfloat16 hi = __float2bfloat16(b);
            __nv_bfloat16 mid = __float2bfloat16(b - __bfloat162float(hi));
            d_Bhi[(size_t)s * N + k] = hi;
            d_Bmid[(size_t)s * N + k] = mid;
        }
        if (t == 0) d_cscs[s] = d_csc[col];
    }
}

// ---------------- K4: HMMA GEMM + scaled/masked epilogue + fused stats ------
// 64x64 CTA tile, BK=32, double-buffered SMEM with XOR swizzle, 8 warps of
// 32x16 tiles, 3 bf16 MMAs per k16 (hi*hi + hi*mid + mid*hi) -> fp32 grade.
// Epilogue: per-CTA deterministic stats partial; last CTA reduces 128 triples.
#define TILE_BYTES 16384   // per stage: Ahi 4K | Amid 4K | Bhi 4K | Bmid 4K
__global__ __launch_bounds__(256) void k_gemm_mma(const int* __restrict__ qid,
                                                  const int* __restrict__ sid) {
    __shared__ __align__(128) char sm[2 * TILE_BYTES];
    int tid = threadIdx.x, lane = tid & 31, wid = tid >> 5;
    int bx = blockIdx.x, by = blockIdx.y;
    uint32_t sb = smem_u32(sm);

    int lr = tid >> 2;
    int lc = (tid & 3) * 16;
    uint32_t lsw = (uint32_t)(lr * 64 + lc) ^ ((uint32_t)(lr & 7) << 4);
    const char* pAh = (const char*)d_Ahi  + (size_t)(by * 64 + lr) * 4096 + lc;
    const char* pAm = (const char*)d_Amid + (size_t)(by * 64 + lr) * 4096 + lc;
    const char* pBh = (const char*)d_Bhi  + (size_t)(bx * 64 + lr) * 4096 + lc;
    const char* pBm = (const char*)d_Bmid + (size_t)(bx * 64 + lr) * 4096 + lc;

    float acc[2][2][4];
#pragma unroll
    for (int i = 0; i < 2; i++)
#pragma unroll
        for (int j = 0; j < 2; j++)
#pragma unroll
            for (int k = 0; k < 4; k++) acc[i][j][k] = 0.f;

    int wm = wid & 1, wn = wid >> 1;

    uint4 ra, rb, rc, rd;
    ra = *(const uint4*)(pAh); rb = *(const uint4*)(pAm);
    rc = *(const uint4*)(pBh); rd = *(const uint4*)(pBm);
    *(uint4*)(sm + lsw)         = ra;
    *(uint4*)(sm + 4096 + lsw)  = rb;
    *(uint4*)(sm + 8192 + lsw)  = rc;
    *(uint4*)(sm + 12288 + lsw) = rd;

    for (int kb = 0; kb < 64; kb++) {
        int b = kb & 1;
        if (kb < 63) {
            int o = (kb + 1) * 64;
            ra = *(const uint4*)(pAh + o); rb = *(const uint4*)(pAm + o);
            rc = *(const uint4*)(pBh + o); rd = *(const uint4*)(pBm + o);
        }
        __syncthreads();
        uint32_t base = sb + b * TILE_BYTES;

        uint32_t bh[2][4], bm[2][4];
#pragma unroll
        for (int ni = 0; ni < 2; ni++) {
            int row = wn * 16 + ni * 8 + (lane & 7);
            uint32_t off = (uint32_t)(row * 64 + ((lane >> 3) * 16));
            uint32_t sw = off ^ ((uint32_t)(row & 7) << 4);
            ldsm4(bh[ni], base + 8192 + sw);
            ldsm4(bm[ni], base + 12288 + sw);
        }
#pragma unroll
        for (int k16 = 0; k16 < 2; k16++) {
            uint32_t ah[2][4], am[2][4];
#pragma unroll
            for (int mi = 0; mi < 2; mi++) {
                int row = wm * 32 + mi * 16 + (lane & 15);
                uint32_t off = (uint32_t)(row * 64 + k16 * 32 + ((lane >> 4) * 16));
                uint32_t sw = off ^ ((uint32_t)(row & 7) << 4);
                ldsm4(ah[mi], base + sw);
                ldsm4(am[mi], base + 4096 + sw);
            }
#pragma unroll
            for (int mi = 0; mi < 2; mi++)
#pragma unroll
                for (int ni = 0; ni < 2; ni++) {
                    mma16816(acc[mi][ni], ah[mi], bh[ni][k16 * 2], bh[ni][k16 * 2 + 1]);
                    mma16816(acc[mi][ni], ah[mi], bm[ni][k16 * 2], bm[ni][k16 * 2 + 1]);
                    mma16816(acc[mi][ni], am[mi], bh[ni][k16 * 2], bh[ni][k16 * 2 + 1]);
                }
        }
        if (kb < 63) {
            char* so = sm + (1 - b) * TILE_BYTES;
            *(uint4*)(so + lsw)         = ra;
            *(uint4*)(so + 4096 + lsw)  = rb;
            *(uint4*)(so + 8192 + lsw)  = rc;
            *(uint4*)(so + 12288 + lsw) = rd;
        }
    }

    // epilogue: scale, diag-mask, write gq; accumulate per-thread stats
    float pc = 0.f, ps = 0.f, pq2 = 0.f;
#pragma unroll
    for (int mi = 0; mi < 2; mi++) {
        int r0 = by * 64 + wm * 32 + mi * 16 + (lane >> 2);
#pragma unroll
        for (int half = 0; half < 2; half++) {
            int r = r0 + half * 8;
            float rq = d_rsq[r];
            int qq = qid[r];
#pragma unroll
            for (int ni = 0; ni < 2; ni++) {
                int c0 = bx * 64 + wn * 16 + ni * 8 + (lane & 3) * 2;
                float v0 = acc[mi][ni][half * 2 + 0] * rq * d_cscs[c0];
                float v1 = acc[mi][ni][half * 2 + 1] * rq * d_cscs[c0 + 1];
                if (sid[c0] == qq) v0 = 0.f;
                if (sid[c0 + 1] == qq) v1 = 0.f;
                *(float2*)&d_gq[(size_t)r * S + c0] = make_float2(v0, v1);
                if (v0 > 0.f) pc += 1.f;
                if (v1 > 0.f) pc += 1.f;
                ps += v0 + v1;
                pq2 += v0 * v0 + v1 * v1;
            }
        }
    }
    // deterministic block tree reduction (reuse smem)
    __syncthreads();
    float* r0s = (float*)sm;
    float* r1s = r0s + 256;
    float* r2s = r1s + 256;
    r0s[tid] = pc; r1s[tid] = ps; r2s[tid] = pq2;
    __syncthreads();
    for (int o = 128; o > 0; o >>= 1) {
        if (tid < o) {
            r0s[tid] += r0s[tid + o];
            r1s[tid] += r1s[tid + o];
            r2s[tid] += r2s[tid + o];
        }
        __syncthreads();
    }
    int cta = by * 8 + bx;   // gridDim (8,16) -> 128 CTAs
    if (tid == 0) {
        d_part[cta * 3 + 0] = r0s[0];
        d_part[cta * 3 + 1] = r1s[0];
        d_part[cta * 3 + 2] = r2s[0];
    }
    // last-CTA final reduction (threadFenceReduction pattern)
    __shared__ unsigned int is_last;
    __threadfence();
    if (tid == 0) {
        unsigned int old = atomicAdd(&d_ctr, 1u);
        is_last = (old == 127u) ? 1u : 0u;
    }
    __syncthreads();
    if (is_last) {
        __threadfence();
        float a0 = 0.f, a1 = 0.f, a2 = 0.f;
        if (tid < 128) {
            a0 = d_part[tid * 3 + 0];
            a1 = d_part[tid * 3 + 1];
            a2 = d_part[tid * 3 + 2];
        }
        r0s[tid] = a0; r1s[tid] = a1; r2s[tid] = a2;
        __syncthreads();
        for (int o = 64; o > 0; o >>= 1) {
            if (tid < o) {
                r0s[tid] += r0s[tid + o];
                r1s[tid] += r1s[tid + o];
                r2s[tid] += r2s[tid + o];
            }
            __syncthreads();
        }
        if (tid == 0) {
            d_stats[0] = r0s[0];
            d_stats[1] = r1s[0];
            d_stats[2] = r2s[0];
            d_ctr = 0;   // reset for next graph replay
        }
    }
}

// ---------------- K5: standardize, powers, ELU, row-normalize ---------------
__global__ void k_final(const float* __restrict__ gw,
                        const float* __restrict__ gb,
                        float* __restrict__ out) {
    int q = blockIdx.x, t = threadIdx.x;
    __shared__ float red[256];
    float s0 = d_stats[0], s1 = d_stats[1], s2 = d_stats[2];
    float mean = s1 / s0;
    float var = fmaxf(s2 / s0 - mean * mean, 1e-30f);
    float istd = rsqrtf(var);
    float w0 = gw[0], w1 = gw[1], w2 = gw[2], w3 = gw[3], w4 = gw[4];
    float b = gb[0];

    float y[2];
#pragma unroll
    for (int c = 0; c < 2; c++) {
        float g = d_gq[(size_t)q * S + t + c * 256];
        float yy = 0.f;
        if (g > 0.f) {
            float x = (g - mean) * istd;
            float m = fabsf(x);
            float sq = (m > 0.f) ? copysignf(sqrtf(m), x) : 0.f;
            float xm = x * m;
            float p = b + w0 * x + w1 * sq + w2 * xm + w3 * xm * m + w4 * xm * m * m;
            yy = ((p > 0.f) ? p : expm1f(p)) + 1.f;
        }
        y[c] = yy;
    }
    red[t] = y[0] + y[1];
    __syncthreads();
    for (int o = 128; o > 0; o >>= 1) {
        if (t < o) red[t] += red[t + o];
        __syncthreads();
    }
    float tot = red[0];
    float inv = (tot != 0.f) ? 1.0f / tot : 0.f;
    out[(size_t)q * S + t] = y[0] * inv;
    out[(size_t)q * S + t + 256] = y[1] * inv;
}

// ---------------- launch ----------------------------------------------------
extern "C" void kernel_launch(void* const* d_in, const int* in_sizes, int n_in,
                              void* d_out, int out_size) {
    const float* graph    = (const float*)d_in[0];
    const float* calib_w  = (const float*)d_in[1];
    const float* global_w = (const float*)d_in[2];
    const float* global_b = (const float*)d_in[3];
    const float* col_w    = (const float*)d_in[4];
    const int*   qid      = (const int*)d_in[5];
    const int*   sid      = (const int*)d_in[6];
    float* out = (float*)d_out;

    k_prep<<<17, 256>>>(calib_w, col_w);
    k_calib<<<256, 256>>>(graph);
    k_colsum_scales<<<8, 256>>>();
    k_gather<<<Q + S, 256>>>(qid, sid);
    k_gemm_mma<<<dim3(8, 16), 256>>>(qid, sid);
    k_final<<<Q, 256>>>(global_w, global_b, out);
}

// round 8
// speedup vs baseline: 3.3478x; 1.1319x over previous
#include <cuda_runtime.h>
#include <cuda_bf16.h>
#include <cstdint>
#include <math.h>

#define N 2048
#define Q 1024
#define S 512
#define NBINS 20
#define FTAB 8192

// ---------------- scratch (device globals; no allocation allowed) ----------
__device__ __nv_bfloat16 d_Ghi[(size_t)N * N];   // calibrated graph, bf16 hi
__device__ __nv_bfloat16 d_Gmid[(size_t)N * N];  // calibrated graph, bf16 mid
__device__ float d_rowsum[N];
__device__ float d_cp[256 * N];                  // per-calib-block column partials
__device__ float d_rs[N];
__device__ float d_csc[N];
__device__ float d_t[N];
__device__ float d_cw[N];
__device__ float d_ftab[FTAB + 1];
__device__ __nv_bfloat16 d_Bthi[(size_t)N * S];  // B^T gathered: [k][s], t-folded
__device__ __nv_bfloat16 d_Btmid[(size_t)N * S];
__device__ float d_gq[(size_t)Q * S];
__device__ float d_part[128 * 3];
__device__ float d_stats[3];
__device__ unsigned int d_ctr = 0;

// ---------------- helpers ---------------------------------------------------
__device__ __forceinline__ uint32_t smem_u32(const void* p) {
    uint32_t a;
    asm("{ .reg .u64 t; cvta.to.shared.u64 t, %1; cvt.u32.u64 %0, t; }"
        : "=r"(a) : "l"(p));
    return a;
}
__device__ __forceinline__ void ldsm4(uint32_t (&r)[4], uint32_t addr) {
    asm volatile(
        "ldmatrix.sync.aligned.m8n8.x4.shared.b16 {%0,%1,%2,%3}, [%4];"
        : "=r"(r[0]), "=r"(r[1]), "=r"(r[2]), "=r"(r[3]) : "r"(addr));
}
__device__ __forceinline__ void ldsm4t(uint32_t (&r)[4], uint32_t addr) {
    asm volatile(
        "ldmatrix.sync.aligned.m8n8.x4.trans.shared.b16 {%0,%1,%2,%3}, [%4];"
        : "=r"(r[0]), "=r"(r[1]), "=r"(r[2]), "=r"(r[3]) : "r"(addr));
}
__device__ __forceinline__ void mma16816(float (&d)[4], const uint32_t (&a)[4],
                                         uint32_t b0, uint32_t b1) {
    asm volatile(
        "mma.sync.aligned.m16n8k16.row.col.f32.bf16.bf16.f32 "
        "{%0,%1,%2,%3}, {%4,%5,%6,%7}, {%8,%9}, {%0,%1,%2,%3};"
        : "+f"(d[0]), "+f"(d[1]), "+f"(d[2]), "+f"(d[3])
        : "r"(a[0]), "r"(a[1]), "r"(a[2]), "r"(a[3]), "r"(b0), "r"(b1));
}

// ---------------- K0: probs+table (blocks 0-15), cw softmax (block 16) ------
__global__ void k_prep(const float* __restrict__ calib_w,
                       const float* __restrict__ colw) {
    int t = threadIdx.x;
    if (blockIdx.x < 16) {
        float w[NBINS];
#pragma unroll
        for (int i = 0; i < NBINS; i++) w[i] = calib_w[i];
        float mx = w[0];
#pragma unroll
        for (int i = 1; i < NBINS; i++) mx = fmaxf(mx, w[i]);
        float e[NBINS], s = 0.f;
#pragma unroll
        for (int i = 0; i < NBINS; i++) { e[i] = expf(w[i] - mx); s += e[i]; }
        float inv = 1.0f / s;
        for (int i = blockIdx.x * 256 + t; i <= FTAB; i += 16 * 256) {
            float g = (float)i * (1.0f / FTAB);
            float zs = 0.f, zp = 0.f;
#pragma unroll
            for (int k = 0; k < NBINS; k++) {
                float d = g - (float)k * (1.0f / 19.0f);
                float z = expf(-d * d * 950.0f);
                zs += z;
                zp += z * (e[k] * inv);
            }
            d_ftab[i] = zp / zs;
        }
    } else {
        __shared__ float red[256];
        float mx = -1e30f;
        for (int j = t; j < N; j += 256) mx = fmaxf(mx, colw[j]);
        red[t] = mx; __syncthreads();
        for (int o = 128; o > 0; o >>= 1) {
            if (t < o) red[t] = fmaxf(red[t], red[t + o]);
            __syncthreads();
        }
        mx = red[0]; __syncthreads();
        float s = 0.f;
        for (int j = t; j < N; j += 256) s += expf(colw[j] - mx);
        red[t] = s; __syncthreads();
        for (int o = 128; o > 0; o >>= 1) {
            if (t < o) red[t] += red[t + o];
            __syncthreads();
        }
        float inv = (float)N / red[0];
        for (int j = t; j < N; j += 256) d_cw[j] = expf(colw[j] - mx) * inv;
    }
}

// ---------------- K1: calibration -> split bf16, row sums, column partials --
__global__ __launch_bounds__(256) void k_calib(const float* __restrict__ graph) {
    __shared__ float tab[FTAB + 1];
    __shared__ float red[256];
    int t = threadIdx.x;
    for (int i = t; i <= FTAB; i += 256) tab[i] = d_ftab[i];
    __syncthreads();
    int row0 = blockIdx.x * 8;
    float colacc[8] = {0.f, 0.f, 0.f, 0.f, 0.f, 0.f, 0.f, 0.f};
    for (int r = 0; r < 8; r++) {
        const float* grow = graph + (size_t)(row0 + r) * N;
        __nv_bfloat16* ohi = d_Ghi + (size_t)(row0 + r) * N;
        __nv_bfloat16* omid = d_Gmid + (size_t)(row0 + r) * N;
        float rsum = 0.f;
#pragma unroll
        for (int c = 0; c < 8; c++) {
            int j = t + c * 256;
            float g = grow[j];
            float out = 0.f;
            if (g > 0.f) {
                float u = g * (float)FTAB;
                int i = min((int)u, FTAB - 1);
                float fr = u - (float)i;
                float f0 = tab[i], f1 = tab[i + 1];
                out = f0 + fr * (f1 - f0);
            }
            __nv_bfloat16 hi = __float2bfloat16(out);
            ohi[j] = hi;
            omid[j] = __float2bfloat16(out - __bfloat162float(hi));
            rsum += out;
            colacc[c] += out;
        }
        red[t] = rsum; __syncthreads();
        for (int o = 128; o > 0; o >>= 1) {
            if (t < o) red[t] += red[t + o];
            __syncthreads();
        }
        if (t == 0) d_rowsum[row0 + r] = red[0];
        __syncthreads();
    }
#pragma unroll
    for (int c = 0; c < 8; c++)
        d_cp[blockIdx.x * N + t + c * 256] = colacc[c];
}

// ---------------- K2: column sums + per-index scales ------------------------
__global__ void k_colsum_scales() {
    int j = blockIdx.x * 256 + threadIdx.x;
    float cs = 0.f;
#pragma unroll 8
    for (int p = 0; p < 256; p++) cs += d_cp[p * N + j];
    float rsum = d_rowsum[j];
    float rs = (rsum > 0.f) ? rsqrtf(rsum) : 0.f;
    float cc = (cs > 0.f) ? rsqrtf(cs) : 0.f;
    float csc = cc * d_cw[j];
    d_rs[j] = rs;
    d_csc[j] = csc;
    d_t[j] = rs * csc;
}

// ---------------- K3: B gather, transposed [k][s], t[k] folded, coalesced ---
__global__ __launch_bounds__(256) void k_gatherB(const int* __restrict__ sid) {
    __shared__ int ss[S];
    int t = threadIdx.x;
    ss[t] = sid[t];
    ss[t + 256] = sid[t + 256];
    __syncthreads();
    int k0 = blockIdx.x * 8;
    for (int r = 0; r < 8; r++) {
        int k = k0 + r;
        float tk = d_t[k];
        const __nv_bfloat16* gh = d_Ghi + (size_t)k * N;
        const __nv_bfloat16* gm = d_Gmid + (size_t)k * N;
#pragma unroll
        for (int c = 0; c < 2; c++) {
            int s = t + c * 256;
            int col = ss[s];
            float v = (__bfloat162float(gh[col]) + __bfloat162float(gm[col])) * tk;
            __nv_bfloat16 hi = __float2bfloat16(v);
            d_Bthi[(size_t)k * S + s] = hi;
            d_Btmid[(size_t)k * S + s] = __float2bfloat16(v - __bfloat162float(hi));
        }
    }
}

// ---------------- K4: HMMA GEMM + epilogue + fused stats --------------------
// A read in place from Ghi/Gmid via qid row indirection (row-major [m][k]).
// B read from Bthi/Btmid [k][s]; fragments via ldmatrix.x4.trans.
// Smem per stage: Ahi 4K | Amid 4K | Bhi 4K | Bmid 4K (B tile = [32k][64n]).
#define TILE_BYTES 16384
__global__ __launch_bounds__(256) void k_gemm_mma(const int* __restrict__ qid,
                                                  const int* __restrict__ sid) {
    __shared__ __align__(128) char sm[2 * TILE_BYTES];
    int tid = threadIdx.x, lane = tid & 31, wid = tid >> 5;
    int bx = blockIdx.x, by = blockIdx.y;
    uint32_t sb = smem_u32(sm);

    // A gmem->smem: thread -> (row lr of 64, 16B chunk lc) of 64x64B tile
    int lr = tid >> 2;
    int lc = (tid & 3) * 16;
    uint32_t lswA = (uint32_t)(lr * 64 + lc) ^ ((uint32_t)(lr & 7) << 4);
    int aRow = qid[by * 64 + lr];   // row indirection
    const char* pAh = (const char*)d_Ghi  + (size_t)aRow * 4096 + lc;
    const char* pAm = (const char*)d_Gmid + (size_t)aRow * 4096 + lc;
    // B gmem->smem: thread -> (k-row lrB of 32, 16B chunk lcB of 128B row)
    int lrB = tid >> 3;
    int lcB = (tid & 7) * 16;
    uint32_t lswB = (uint32_t)(lrB * 128 + lcB) ^ ((uint32_t)(lrB & 7) << 4);
    const char* pBh = (const char*)d_Bthi  + (size_t)lrB * 1024 + bx * 128 + lcB;
    const char* pBm = (const char*)d_Btmid + (size_t)lrB * 1024 + bx * 128 + lcB;

    float acc[2][2][4];
#pragma unroll
    for (int i = 0; i < 2; i++)
#pragma unroll
        for (int j = 0; j < 2; j++)
#pragma unroll
            for (int k = 0; k < 4; k++) acc[i][j][k] = 0.f;

    int wm = wid & 1, wn = wid >> 1;

    uint4 ra, rb, rc, rd;
    ra = *(const uint4*)(pAh); rb = *(const uint4*)(pAm);
    rc = *(const uint4*)(pBh); rd = *(const uint4*)(pBm);
    *(uint4*)(sm + lswA)         = ra;
    *(uint4*)(sm + 4096 + lswA)  = rb;
    *(uint4*)(sm + 8192 + lswB)  = rc;
    *(uint4*)(sm + 12288 + lswB) = rd;

    for (int kb = 0; kb < 64; kb++) {
        int b = kb & 1;
        if (kb < 63) {
            int oA = (kb + 1) * 64;        // +32 k * 2B along A row
            int oB = (kb + 1) * 32768;     // +32 k rows * 1024B along Bt
            ra = *(const uint4*)(pAh + oA); rb = *(const uint4*)(pAm + oA);
            rc = *(const uint4*)(pBh + oB); rd = *(const uint4*)(pBm + oB);
        }
        __syncthreads();
        uint32_t base = sb + b * TILE_BYTES;

        // B fragments: ldmatrix.x4.trans over [k32][n8] per ni
        uint32_t bh[2][4], bm[2][4];
#pragma unroll
        for (int ni = 0; ni < 2; ni++) {
            uint32_t off = (uint32_t)(lane * 128 + wn * 32 + ni * 16);
            uint32_t sw = off ^ ((uint32_t)(lane & 7) << 4);
            ldsm4t(bh[ni], base + 8192 + sw);
            ldsm4t(bm[ni], base + 12288 + sw);
        }
#pragma unroll
        for (int k16 = 0; k16 < 2; k16++) {
            uint32_t ah[2][4], am[2][4];
#pragma unroll
            for (int mi = 0; mi < 2; mi++) {
                int row = wm * 32 + mi * 16 + (lane & 15);
                uint32_t off = (uint32_t)(row * 64 + k16 * 32 + ((lane >> 4) * 16));
                uint32_t sw = off ^ ((uint32_t)(row & 7) << 4);
                ldsm4(ah[mi], base + sw);
                ldsm4(am[mi], base + 4096 + sw);
            }
#pragma unroll
            for (int mi = 0; mi < 2; mi++)
#pragma unroll
                for (int ni = 0; ni < 2; ni++) {
                    mma16816(acc[mi][ni], ah[mi], bh[ni][k16 * 2], bh[ni][k16 * 2 + 1]);
                    mma16816(acc[mi][ni], ah[mi], bm[ni][k16 * 2], bm[ni][k16 * 2 + 1]);
                    mma16816(acc[mi][ni], am[mi], bh[ni][k16 * 2], bh[ni][k16 * 2 + 1]);
                }
        }
        if (kb < 63) {
            char* so = sm + (1 - b) * TILE_BYTES;
            *(uint4*)(so + lswA)         = ra;
            *(uint4*)(so + 4096 + lswA)  = rb;
            *(uint4*)(so + 8192 + lswB)  = rc;
            *(uint4*)(so + 12288 + lswB) = rd;
        }
    }

    // epilogue: per-thread fixed columns
    int c0 = bx * 64 + wn * 16 + (lane & 3) * 2;   // ni=0 pair
    int sdA0 = sid[c0], sdA1 = sid[c0 + 1];
    int sdB0 = sid[c0 + 8], sdB1 = sid[c0 + 9];
    float csA0 = d_csc[sdA0], csA1 = d_csc[sdA1];
    float csB0 = d_csc[sdB0], csB1 = d_csc[sdB1];

    float pc = 0.f, ps = 0.f, pq2 = 0.f;
#pragma unroll
    for (int mi = 0; mi < 2; mi++) {
        int r0 = by * 64 + wm * 32 + mi * 16 + (lane >> 2);
#pragma unroll
        for (int half = 0; half < 2; half++) {
            int r = r0 + half * 8;
            int qq = qid[r];
            float rq = d_rs[qq];
            {
                float v0 = acc[mi][0][half * 2 + 0] * rq * csA0;
                float v1 = acc[mi][0][half * 2 + 1] * rq * csA1;
                if (sdA0 == qq) v0 = 0.f;
                if (sdA1 == qq) v1 = 0.f;
                *(float2*)&d_gq[(size_t)r * S + c0] = make_float2(v0, v1);
                if (v0 > 0.f) pc += 1.f;
                if (v1 > 0.f) pc += 1.f;
                ps += v0 + v1;
                pq2 += v0 * v0 + v1 * v1;
            }
            {
                float v0 = acc[mi][1][half * 2 + 0] * rq * csB0;
                float v1 = acc[mi][1][half * 2 + 1] * rq * csB1;
                if (sdB0 == qq) v0 = 0.f;
                if (sdB1 == qq) v1 = 0.f;
                *(float2*)&d_gq[(size_t)r * S + c0 + 8] = make_float2(v0, v1);
                if (v0 > 0.f) pc += 1.f;
                if (v1 > 0.f) pc += 1.f;
                ps += v0 + v1;
                pq2 += v0 * v0 + v1 * v1;
            }
        }
    }
    // deterministic block tree reduction (reuse smem)
    __syncthreads();
    float* r0s = (float*)sm;
    float* r1s = r0s + 256;
    float* r2s = r1s + 256;
    r0s[tid] = pc; r1s[tid] = ps; r2s[tid] = pq2;
    __syncthreads();
    for (int o = 128; o > 0; o >>= 1) {
        if (tid < o) {
            r0s[tid] += r0s[tid + o];
            r1s[tid] += r1s[tid + o];
            r2s[tid] += r2s[tid + o];
        }
        __syncthreads();
    }
    int cta = by * 8 + bx;
    if (tid == 0) {
        d_part[cta * 3 + 0] = r0s[0];
        d_part[cta * 3 + 1] = r1s[0];
        d_part[cta * 3 + 2] = r2s[0];
    }
    __shared__ unsigned int is_last;
    __threadfence();
    if (tid == 0) {
        unsigned int old = atomicAdd(&d_ctr, 1u);
        is_last = (old == 127u) ? 1u : 0u;
    }
    __syncthreads();
    if (is_last) {
        __threadfence();
        float a0 = 0.f, a1 = 0.f, a2 = 0.f;
        if (tid < 128) {
            a0 = d_part[tid * 3 + 0];
            a1 = d_part[tid * 3 + 1];
            a2 = d_part[tid * 3 + 2];
        }
        r0s[tid] = a0; r1s[tid] = a1; r2s[tid] = a2;
        __syncthreads();
        for (int o = 64; o > 0; o >>= 1) {
            if (tid < o) {
                r0s[tid] += r0s[tid + o];
                r1s[tid] += r1s[tid + o];
                r2s[tid] += r2s[tid + o];
            }
            __syncthreads();
        }
        if (tid == 0) {
            d_stats[0] = r0s[0];
            d_stats[1] = r1s[0];
            d_stats[2] = r2s[0];
            d_ctr = 0;
        }
    }
}

// ---------------- K5: standardize, powers, ELU, row-normalize ---------------
__global__ void k_final(const float* __restrict__ gw,
                        const float* __restrict__ gb,
                        float* __restrict__ out) {
    int q = blockIdx.x, t = threadIdx.x;
    __shared__ float red[256];
    float s0 = d_stats[0], s1 = d_stats[1], s2 = d_stats[2];
    float mean = s1 / s0;
    float var = fmaxf(s2 / s0 - mean * mean, 1e-30f);
    float istd = rsqrtf(var);
    float w0 = gw[0], w1 = gw[1], w2 = gw[2], w3 = gw[3], w4 = gw[4];
    float b = gb[0];

    float y[2];
#pragma unroll
    for (int c = 0; c < 2; c++) {
        float g = d_gq[(size_t)q * S + t + c * 256];
        float yy = 0.f;
        if (g > 0.f) {
            float x = (g - mean) * istd;
            float m = fabsf(x);
            float sq = (m > 0.f) ? copysignf(sqrtf(m), x) : 0.f;
            float xm = x * m;
            float p = b + w0 * x + w1 * sq + w2 * xm + w3 * xm * m + w4 * xm * m * m;
            yy = ((p > 0.f) ? p : expm1f(p)) + 1.f;
        }
        y[c] = yy;
    }
    red[t] = y[0] + y[1];
    __syncthreads();
    for (int o = 128; o > 0; o >>= 1) {
        if (t < o) red[t] += red[t + o];
        __syncthreads();
    }
    float tot = red[0];
    float inv = (tot != 0.f) ? 1.0f / tot : 0.f;
    out[(size_t)q * S + t] = y[0] * inv;
    out[(size_t)q * S + t + 256] = y[1] * inv;
}

// ---------------- launch ----------------------------------------------------
extern "C" void kernel_launch(void* const* d_in, const int* in_sizes, int n_in,
                              void* d_out, int out_size) {
    const float* graph    = (const float*)d_in[0];
    const float* calib_w  = (const float*)d_in[1];
    const float* global_w = (const float*)d_in[2];
    const float* global_b = (const float*)d_in[3];
    const float* col_w    = (const float*)d_in[4];
    const int*   qid      = (const int*)d_in[5];
    const int*   sid      = (const int*)d_in[6];
    float* out = (float*)d_out;

    k_prep<<<17, 256>>>(calib_w, col_w);
    k_calib<<<256, 256>>>(graph);
    k_colsum_scales<<<8, 256>>>();
    k_gatherB<<<256, 256>>>(sid);
    k_gemm_mma<<<dim3(8, 16), 256>>>(qid, sid);
    k_final<<<Q, 256>>>(global_w, global_b, out);
}

// round 9
// speedup vs baseline: 3.3653x; 1.0052x over previous
#include <cuda_runtime.h>
#include <cuda_bf16.h>
#include <cstdint>
#include <math.h>

#define N 2048
#define Q 1024
#define S 512
#define NBINS 20
#define FTAB 8192

// ---------------- scratch (device globals; no allocation allowed) ----------
__device__ __nv_bfloat16 d_Ghi[(size_t)N * N];   // calibrated graph, bf16 hi
__device__ __nv_bfloat16 d_Gmid[(size_t)N * N];  // calibrated graph, bf16 mid
__device__ float d_rowsum[N];
__device__ float d_cp[256 * N];                  // per-calib-block column partials
__device__ float d_rs[N];
__device__ float d_csc[N];
__device__ float d_t[N];
__device__ float d_cw[N];
__device__ float d_ftab[FTAB + 1];
__device__ __nv_bfloat16 d_Bthi[(size_t)N * S];  // B^T gathered: [k][s], t-folded
__device__ __nv_bfloat16 d_Btmid[(size_t)N * S];
__device__ float d_gq[(size_t)Q * S];
__device__ float d_part[128 * 3];
__device__ float d_stats[3];
__device__ unsigned int d_ctr = 0;

// ---------------- helpers ---------------------------------------------------
__device__ __forceinline__ uint32_t smem_u32(const void* p) {
    uint32_t a;
    asm("{ .reg .u64 t; cvta.to.shared.u64 t, %1; cvt.u32.u64 %0, t; }"
        : "=r"(a) : "l"(p));
    return a;
}
__device__ __forceinline__ void ldsm4(uint32_t (&r)[4], uint32_t addr) {
    asm volatile(
        "ldmatrix.sync.aligned.m8n8.x4.shared.b16 {%0,%1,%2,%3}, [%4];"
        : "=r"(r[0]), "=r"(r[1]), "=r"(r[2]), "=r"(r[3]) : "r"(addr));
}
__device__ __forceinline__ void ldsm4t(uint32_t (&r)[4], uint32_t addr) {
    asm volatile(
        "ldmatrix.sync.aligned.m8n8.x4.trans.shared.b16 {%0,%1,%2,%3}, [%4];"
        : "=r"(r[0]), "=r"(r[1]), "=r"(r[2]), "=r"(r[3]) : "r"(addr));
}
__device__ __forceinline__ void mma16816(float (&d)[4], const uint32_t (&a)[4],
                                         uint32_t b0, uint32_t b1) {
    asm volatile(
        "mma.sync.aligned.m16n8k16.row.col.f32.bf16.bf16.f32 "
        "{%0,%1,%2,%3}, {%4,%5,%6,%7}, {%8,%9}, {%0,%1,%2,%3};"
        : "+f"(d[0]), "+f"(d[1]), "+f"(d[2]), "+f"(d[3])
        : "r"(a[0]), "r"(a[1]), "r"(a[2]), "r"(a[3]), "r"(b0), "r"(b1));
}

// ---------------- K0: probs+table (blocks 0-15), cw softmax (block 16) ------
__global__ void k_prep(const float* __restrict__ calib_w,
                       const float* __restrict__ colw) {
    int t = threadIdx.x;
    if (blockIdx.x < 16) {
        float w[NBINS];
#pragma unroll
        for (int i = 0; i < NBINS; i++) w[i] = calib_w[i];
        float mx = w[0];
#pragma unroll
        for (int i = 1; i < NBINS; i++) mx = fmaxf(mx, w[i]);
        float e[NBINS], s = 0.f;
#pragma unroll
        for (int i = 0; i < NBINS; i++) { e[i] = expf(w[i] - mx); s += e[i]; }
        float inv = 1.0f / s;
        for (int i = blockIdx.x * 256 + t; i <= FTAB; i += 16 * 256) {
            float g = (float)i * (1.0f / FTAB);
            float zs = 0.f, zp = 0.f;
#pragma unroll
            for (int k = 0; k < NBINS; k++) {
                float d = g - (float)k * (1.0f / 19.0f);
                float z = expf(-d * d * 950.0f);
                zs += z;
                zp += z * (e[k] * inv);
            }
            d_ftab[i] = zp / zs;
        }
    } else {
        __shared__ float red[256];
        float mx = -1e30f;
        for (int j = t; j < N; j += 256) mx = fmaxf(mx, colw[j]);
        red[t] = mx; __syncthreads();
        for (int o = 128; o > 0; o >>= 1) {
            if (t < o) red[t] = fmaxf(red[t], red[t + o]);
            __syncthreads();
        }
        mx = red[0]; __syncthreads();
        float s = 0.f;
        for (int j = t; j < N; j += 256) s += expf(colw[j] - mx);
        red[t] = s; __syncthreads();
        for (int o = 128; o > 0; o >>= 1) {
            if (t < o) red[t] += red[t + o];
            __syncthreads();
        }
        float inv = (float)N / red[0];
        for (int j = t; j < N; j += 256) d_cw[j] = expf(colw[j] - mx) * inv;
    }
}

// ---------------- K1: calibration -> split bf16, row sums, column partials --
__global__ __launch_bounds__(256) void k_calib(const float* __restrict__ graph) {
    __shared__ float tab[FTAB + 1];
    __shared__ float red[256];
    int t = threadIdx.x;
    for (int i = t; i <= FTAB; i += 256) tab[i] = d_ftab[i];
    __syncthreads();
    int row0 = blockIdx.x * 8;
    float colacc[8] = {0.f, 0.f, 0.f, 0.f, 0.f, 0.f, 0.f, 0.f};
    for (int r = 0; r < 8; r++) {
        const float* grow = graph + (size_t)(row0 + r) * N;
        __nv_bfloat16* ohi = d_Ghi + (size_t)(row0 + r) * N;
        __nv_bfloat16* omid = d_Gmid + (size_t)(row0 + r) * N;
        float rsum = 0.f;
#pragma unroll
        for (int c = 0; c < 8; c++) {
            int j = t + c * 256;
            float g = grow[j];
            float out = 0.f;
            if (g > 0.f) {
                float u = g * (float)FTAB;
                int i = min((int)u, FTAB - 1);
                float fr = u - (float)i;
                float f0 = tab[i], f1 = tab[i + 1];
                out = f0 + fr * (f1 - f0);
            }
            __nv_bfloat16 hi = __float2bfloat16(out);
            ohi[j] = hi;
            omid[j] = __float2bfloat16(out - __bfloat162float(hi));
            rsum += out;
            colacc[c] += out;
        }
        red[t] = rsum; __syncthreads();
        for (int o = 128; o > 0; o >>= 1) {
            if (t < o) red[t] += red[t + o];
            __syncthreads();
        }
        if (t == 0) d_rowsum[row0 + r] = red[0];
        __syncthreads();
    }
#pragma unroll
    for (int c = 0; c < 8; c++)
        d_cp[blockIdx.x * N + t + c * 256] = colacc[c];
}

// ---------------- K2: column sums + per-index scales ------------------------
__global__ void k_colsum_scales() {
    int j = blockIdx.x * 256 + threadIdx.x;
    float cs = 0.f;
#pragma unroll 8
    for (int p = 0; p < 256; p++) cs += d_cp[p * N + j];
    float rsum = d_rowsum[j];
    float rs = (rsum > 0.f) ? rsqrtf(rsum) : 0.f;
    float cc = (cs > 0.f) ? rsqrtf(cs) : 0.f;
    float csc = cc * d_cw[j];
    d_rs[j] = rs;
    d_csc[j] = csc;
    d_t[j] = rs * csc;
}

// ---------------- K3: B gather, one k-row per block, fully parallel ---------
__global__ __launch_bounds__(256) void k_gatherB(const int* __restrict__ sid) {
    int t = threadIdx.x;
    int k = blockIdx.x;
    float tk = d_t[k];
    const __nv_bfloat16* gh = d_Ghi + (size_t)k * N;
    const __nv_bfloat16* gm = d_Gmid + (size_t)k * N;
    int s0 = t, s1 = t + 256;
    int c0 = sid[s0], c1 = sid[s1];
    float h0 = __bfloat162float(gh[c0]);
    float h1 = __bfloat162float(gh[c1]);
    float m0 = __bfloat162float(gm[c0]);
    float m1 = __bfloat162float(gm[c1]);
    float v0 = (h0 + m0) * tk;
    float v1 = (h1 + m1) * tk;
    __nv_bfloat16 hi0 = __float2bfloat16(v0);
    __nv_bfloat16 hi1 = __float2bfloat16(v1);
    d_Bthi[(size_t)k * S + s0] = hi0;
    d_Bthi[(size_t)k * S + s1] = hi1;
    d_Btmid[(size_t)k * S + s0] = __float2bfloat16(v0 - __bfloat162float(hi0));
    d_Btmid[(size_t)k * S + s1] = __float2bfloat16(v1 - __bfloat162float(hi1));
}

// ---------------- K4: HMMA GEMM + epilogue + fused stats --------------------
// A read in place from Ghi/Gmid via qid row indirection (row-major [m][k]).
// B read from Bthi/Btmid [k][s]; fragments via ldmatrix.x4.trans.
// Smem per stage: Ahi 4K | Amid 4K | Bhi 4K | Bmid 4K (B tile = [32k][64n]).
#define TILE_BYTES 16384
__global__ __launch_bounds__(256) void k_gemm_mma(const int* __restrict__ qid,
                                                  const int* __restrict__ sid) {
    __shared__ __align__(128) char sm[2 * TILE_BYTES];
    int tid = threadIdx.x, lane = tid & 31, wid = tid >> 5;
    int bx = blockIdx.x, by = blockIdx.y;
    uint32_t sb = smem_u32(sm);

    // A gmem->smem: thread -> (row lr of 64, 16B chunk lc) of 64x64B tile
    int lr = tid >> 2;
    int lc = (tid & 3) * 16;
    uint32_t lswA = (uint32_t)(lr * 64 + lc) ^ ((uint32_t)(lr & 7) << 4);
    int aRow = qid[by * 64 + lr];   // row indirection
    const char* pAh = (const char*)d_Ghi  + (size_t)aRow * 4096 + lc;
    const char* pAm = (const char*)d_Gmid + (size_t)aRow * 4096 + lc;
    // B gmem->smem: thread -> (k-row lrB of 32, 16B chunk lcB of 128B row)
    int lrB = tid >> 3;
    int lcB = (tid & 7) * 16;
    uint32_t lswB = (uint32_t)(lrB * 128 + lcB) ^ ((uint32_t)(lrB & 7) << 4);
    const char* pBh = (const char*)d_Bthi  + (size_t)lrB * 1024 + bx * 128 + lcB;
    const char* pBm = (const char*)d_Btmid + (size_t)lrB * 1024 + bx * 128 + lcB;

    float acc[2][2][4];
#pragma unroll
    for (int i = 0; i < 2; i++)
#pragma unroll
        for (int j = 0; j < 2; j++)
#pragma unroll
            for (int k = 0; k < 4; k++) acc[i][j][k] = 0.f;

    int wm = wid & 1, wn = wid >> 1;

    uint4 ra, rb, rc, rd;
    ra = *(const uint4*)(pAh); rb = *(const uint4*)(pAm);
    rc = *(const uint4*)(pBh); rd = *(const uint4*)(pBm);
    *(uint4*)(sm + lswA)         = ra;
    *(uint4*)(sm + 4096 + lswA)  = rb;
    *(uint4*)(sm + 8192 + lswB)  = rc;
    *(uint4*)(sm + 12288 + lswB) = rd;

    for (int kb = 0; kb < 64; kb++) {
        int b = kb & 1;
        if (kb < 63) {
            int oA = (kb + 1) * 64;        // +32 k * 2B along A row
            int oB = (kb + 1) * 32768;     // +32 k rows * 1024B along Bt
            ra = *(const uint4*)(pAh + oA); rb = *(const uint4*)(pAm + oA);
            rc = *(const uint4*)(pBh + oB); rd = *(const uint4*)(pBm + oB);
        }
        __syncthreads();
        uint32_t base = sb + b * TILE_BYTES;

        // B fragments: ldmatrix.x4.trans over [k32][n8] per ni
        uint32_t bh[2][4], bm[2][4];
#pragma unroll
        for (int ni = 0; ni < 2; ni++) {
            uint32_t off = (uint32_t)(lane * 128 + wn * 32 + ni * 16);
            uint32_t sw = off ^ ((uint32_t)(lane & 7) << 4);
            ldsm4t(bh[ni], base + 8192 + sw);
            ldsm4t(bm[ni], base + 12288 + sw);
        }
#pragma unroll
        for (int k16 = 0; k16 < 2; k16++) {
            uint32_t ah[2][4], am[2][4];
#pragma unroll
            for (int mi = 0; mi < 2; mi++) {
                int row = wm * 32 + mi * 16 + (lane & 15);
                uint32_t off = (uint32_t)(row * 64 + k16 * 32 + ((lane >> 4) * 16));
                uint32_t sw = off ^ ((uint32_t)(row & 7) << 4);
                ldsm4(ah[mi], base + sw);
                ldsm4(am[mi], base + 4096 + sw);
            }
#pragma unroll
            for (int mi = 0; mi < 2; mi++)
#pragma unroll
                for (int ni = 0; ni < 2; ni++) {
                    mma16816(acc[mi][ni], ah[mi], bh[ni][k16 * 2], bh[ni][k16 * 2 + 1]);
                    mma16816(acc[mi][ni], ah[mi], bm[ni][k16 * 2], bm[ni][k16 * 2 + 1]);
                    mma16816(acc[mi][ni], am[mi], bh[ni][k16 * 2], bh[ni][k16 * 2 + 1]);
                }
        }
        if (kb < 63) {
            char* so = sm + (1 - b) * TILE_BYTES;
            *(uint4*)(so + lswA)         = ra;
            *(uint4*)(so + 4096 + lswA)  = rb;
            *(uint4*)(so + 8192 + lswB)  = rc;
            *(uint4*)(so + 12288 + lswB) = rd;
        }
    }

    // epilogue: per-thread fixed columns
    int c0 = bx * 64 + wn * 16 + (lane & 3) * 2;   // ni=0 pair
    int sdA0 = sid[c0], sdA1 = sid[c0 + 1];
    int sdB0 = sid[c0 + 8], sdB1 = sid[c0 + 9];
    float csA0 = d_csc[sdA0], csA1 = d_csc[sdA1];
    float csB0 = d_csc[sdB0], csB1 = d_csc[sdB1];

    float pc = 0.f, ps = 0.f, pq2 = 0.f;
#pragma unroll
    for (int mi = 0; mi < 2; mi++) {
        int r0 = by * 64 + wm * 32 + mi * 16 + (lane >> 2);
#pragma unroll
        for (int half = 0; half < 2; half++) {
            int r = r0 + half * 8;
            int qq = qid[r];
            float rq = d_rs[qq];
            {
                float v0 = acc[mi][0][half * 2 + 0] * rq * csA0;
                float v1 = acc[mi][0][half * 2 + 1] * rq * csA1;
                if (sdA0 == qq) v0 = 0.f;
                if (sdA1 == qq) v1 = 0.f;
                *(float2*)&d_gq[(size_t)r * S + c0] = make_float2(v0, v1);
                if (v0 > 0.f) pc += 1.f;
                if (v1 > 0.f) pc += 1.f;
                ps += v0 + v1;
                pq2 += v0 * v0 + v1 * v1;
            }
            {
                float v0 = acc[mi][1][half * 2 + 0] * rq * csB0;
                float v1 = acc[mi][1][half * 2 + 1] * rq * csB1;
                if (sdB0 == qq) v0 = 0.f;
                if (sdB1 == qq) v1 = 0.f;
                *(float2*)&d_gq[(size_t)r * S + c0 + 8] = make_float2(v0, v1);
                if (v0 > 0.f) pc += 1.f;
                if (v1 > 0.f) pc += 1.f;
                ps += v0 + v1;
                pq2 += v0 * v0 + v1 * v1;
            }
        }
    }
    // deterministic block tree reduction (reuse smem)
    __syncthreads();
    float* r0s = (float*)sm;
    float* r1s = r0s + 256;
    float* r2s = r1s + 256;
    r0s[tid] = pc; r1s[tid] = ps; r2s[tid] = pq2;
    __syncthreads();
    for (int o = 128; o > 0; o >>= 1) {
        if (tid < o) {
            r0s[tid] += r0s[tid + o];
            r1s[tid] += r1s[tid + o];
            r2s[tid] += r2s[tid + o];
        }
        __syncthreads();
    }
    int cta = by * 8 + bx;
    if (tid == 0) {
        d_part[cta * 3 + 0] = r0s[0];
        d_part[cta * 3 + 1] = r1s[0];
        d_part[cta * 3 + 2] = r2s[0];
    }
    __shared__ unsigned int is_last;
    __threadfence();
    if (tid == 0) {
        unsigned int old = atomicAdd(&d_ctr, 1u);
        is_last = (old == 127u) ? 1u : 0u;
    }
    __syncthreads();
    if (is_last) {
        __threadfence();
        float a0 = 0.f, a1 = 0.f, a2 = 0.f;
        if (tid < 128) {
            a0 = d_part[tid * 3 + 0];
            a1 = d_part[tid * 3 + 1];
            a2 = d_part[tid * 3 + 2];
        }
        r0s[tid] = a0; r1s[tid] = a1; r2s[tid] = a2;
        __syncthreads();
        for (int o = 64; o > 0; o >>= 1) {
            if (tid < o) {
                r0s[tid] += r0s[tid + o];
                r1s[tid] += r1s[tid + o];
                r2s[tid] += r2s[tid + o];
            }
            __syncthreads();
        }
        if (tid == 0) {
            d_stats[0] = r0s[0];
            d_stats[1] = r1s[0];
            d_stats[2] = r2s[0];
            d_ctr = 0;
        }
    }
}

// ---------------- K5: standardize, powers, ELU, row-normalize ---------------
__global__ void k_final(const float* __restrict__ gw,
                        const float* __restrict__ gb,
                        float* __restrict__ out) {
    int q = blockIdx.x, t = threadIdx.x;
    __shared__ float red[256];
    float s0 = d_stats[0], s1 = d_stats[1], s2 = d_stats[2];
    float mean = s1 / s0;
    float var = fmaxf(s2 / s0 - mean * mean, 1e-30f);
    float istd = rsqrtf(var);
    float w0 = gw[0], w1 = gw[1], w2 = gw[2], w3 = gw[3], w4 = gw[4];
    float b = gb[0];

    float y[2];
#pragma unroll
    for (int c = 0; c < 2; c++) {
        float g = d_gq[(size_t)q * S + t + c * 256];
        float yy = 0.f;
        if (g > 0.f) {
            float x = (g - mean) * istd;
            float m = fabsf(x);
            float sq = (m > 0.f) ? copysignf(sqrtf(m), x) : 0.f;
            float xm = x * m;
            float p = b + w0 * x + w1 * sq + w2 * xm + w3 * xm * m + w4 * xm * m * m;
            yy = ((p > 0.f) ? p : expm1f(p)) + 1.f;
        }
        y[c] = yy;
    }
    red[t] = y[0] + y[1];
    __syncthreads();
    for (int o = 128; o > 0; o >>= 1) {
        if (t < o) red[t] += red[t + o];
        __syncthreads();
    }
    float tot = red[0];
    float inv = (tot != 0.f) ? 1.0f / tot : 0.f;
    out[(size_t)q * S + t] = y[0] * inv;
    out[(size_t)q * S + t + 256] = y[1] * inv;
}

// ---------------- launch ----------------------------------------------------
extern "C" void kernel_launch(void* const* d_in, const int* in_sizes, int n_in,
                              void* d_out, int out_size) {
    const float* graph    = (const float*)d_in[0];
    const float* calib_w  = (const float*)d_in[1];
    const float* global_w = (const float*)d_in[2];
    const float* global_b = (const float*)d_in[3];
    const float* col_w    = (const float*)d_in[4];
    const int*   qid      = (const int*)d_in[5];
    const int*   sid      = (const int*)d_in[6];
    float* out = (float*)d_out;

    k_prep<<<17, 256>>>(calib_w, col_w);
    k_calib<<<256, 256>>>(graph);
    k_colsum_scales<<<8, 256>>>();
    k_gatherB<<<N, 256>>>(sid);
    k_gemm_mma<<<dim3(8, 16), 256>>>(qid, sid);
    k_final<<<Q, 256>>>(global_w, global_b, out);
}